// round 7
// baseline (speedup 1.0000x reference)
#include <cuda_runtime.h>
#include <stdint.h>

#define N_NODES 100000
#define N_EDGES 1600000
#define N_GRAPHS 256

// ---------------- scratch (no allocation allowed -> device globals) ----------
__device__ int   g_deg_out[N_NODES];
__device__ int   g_deg_in[N_NODES];
__device__ float g_norm_src[N_NODES];
__device__ float g_norm_dst[N_NODES];
__device__ int   g_row[N_NODES + 1];            // CSR row offsets (by dst)
__device__ int   g_cur[N_NODES];                // fill cursors
__device__ int   g_csr[N_EDGES];                // src index per CSR slot
__device__ float g_bufA[(size_t)N_NODES * 128];
__device__ float g_bufB[(size_t)N_NODES * 128];
__device__ int   g_flag_idx;                    // 1 = src/dst are int32
__device__ int   g_flag_gid;                    // 1 = graph_id is int32

// ---------------- helpers ----------------------------------------------------
__device__ __forceinline__ int load_idx(const void* p, long long i, int is32) {
    if (is32) return ((const int*)p)[i];
    return (int)(((const long long*)p)[i]);
}

// init: zero degree arrays; block 0 additionally does dtype detection.
// int64 values < 2^31 -> every odd 32-bit word is 0; int32 data -> nonzero.
// src: scan head window (values random => certain nonzero if int32).
// gid: scan TAIL window within the int32-size bound (gid is sorted ascending,
//      head is legitimately zero; tail holds ~255 if int32, hi-words 0 if int64).
__global__ void init_kernel(const unsigned* __restrict__ s,
                            const unsigned* __restrict__ g) {
    int i = blockIdx.x * blockDim.x + threadIdx.x;
    if (i == 0) { g_flag_idx = 0; g_flag_gid = 0; }
    if (i < N_NODES) { g_deg_out[i] = 0; g_deg_in[i] = 0; }
    if (blockIdx.x == 0) {
        int fi = 0, fg = 0;
        for (int j = threadIdx.x; j < 2048; j += 256)
            if ((j & 1) && s[j]) fi = 1;
        // window [N_NODES-2048, N_NODES) words: in-bounds for both dtypes
        for (int j = N_NODES - 2048 + threadIdx.x; j < N_NODES; j += 256)
            if ((j & 1) && g[j]) fg = 1;
        if (fi) g_flag_idx = 1;
        if (fg) g_flag_gid = 1;
    }
}

__global__ void zero_out_kernel(float* p, int n) {
    int i = blockIdx.x * blockDim.x + threadIdx.x;
    if (i < n) p[i] = 0.0f;
}

// ---------------- degrees ----------------------------------------------------
__global__ void deg_kernel(const void* src, const void* dst) {
    int is32 = g_flag_idx;
    long long i = (long long)blockIdx.x * blockDim.x + threadIdx.x;
    long long stride = (long long)gridDim.x * blockDim.x;
    for (; i < N_EDGES; i += stride) {
        atomicAdd(&g_deg_out[load_idx(src, i, is32)], 1);
        atomicAdd(&g_deg_in[load_idx(dst, i, is32)], 1);
    }
}

// single-block: exclusive scan of deg_in -> row offsets/cursors, plus norms
__global__ void scan_norm_kernel() {
    __shared__ int ssum[1024];
    const int CH = (N_NODES + 1023) / 1024;   // 98
    int t = threadIdx.x;
    int lo = t * CH;
    int hi = min(lo + CH, N_NODES);
    int s = 0;
    for (int i = lo; i < hi; i++) {
        int di = g_deg_in[i];
        int doo = g_deg_out[i];
        s += di;
        g_norm_src[i] = (doo > 0) ? rsqrtf((float)doo) : 0.0f;
        g_norm_dst[i] = (di  > 0) ? rsqrtf((float)di)  : 0.0f;
    }
    ssum[t] = s;
    __syncthreads();
    for (int off = 1; off < 1024; off <<= 1) {
        int v = (t >= off) ? ssum[t - off] : 0;
        __syncthreads();
        ssum[t] += v;
        __syncthreads();
    }
    int run = (t > 0) ? ssum[t - 1] : 0;
    for (int i = lo; i < hi; i++) {
        g_row[i] = run;
        g_cur[i] = run;
        run += g_deg_in[i];
    }
    if (t == 1023) g_row[N_NODES] = ssum[1023];
}

__global__ void fill_csr_kernel(const void* src, const void* dst) {
    int is32 = g_flag_idx;
    long long i = (long long)blockIdx.x * blockDim.x + threadIdx.x;
    long long stride = (long long)gridDim.x * blockDim.x;
    for (; i < N_EDGES; i += stride) {
        int d = load_idx(dst, i, is32);
        int pos = atomicAdd(&g_cur[d], 1);
        g_csr[pos] = load_idx(src, i, is32);
    }
}

// ------- fused layer: gather (CSR) into smem, then GEMM + relu + *norm_src ---
// SCALE_SRC: multiply per-edge by norm_src[src] (layer 1 reading raw h).
// Otherwise x rows are already pre-scaled by the producing epilogue.
// out[n] = relu((sum_e x[src_e] [*ns]) * nd @ W + b) * norm_src[n]
template <int DIN, int DOUT, int SCALE_SRC>
__global__ void fused_layer_kernel(const float* __restrict__ x,
                                   const float* __restrict__ W,
                                   const float* __restrict__ b,
                                   float* __restrict__ out) {
    constexpr int NPB = 16;
    constexpr int K4  = DIN / 4;
    constexpr int TY  = 256 / DOUT;
    constexpr int R   = NPB / TY;
    __shared__ float smf[NPB * DIN];
    int tid  = threadIdx.x;
    int warp = tid >> 5;
    int lane = tid & 31;
    int base = blockIdx.x * NPB;

    // ---- phase A: 8 warps gather 2 nodes each ----
#pragma unroll
    for (int t = 0; t < 2; t++) {
        int n = base + warp * 2 + t;
        int lo = g_row[n], hi = g_row[n + 1];
        if (DIN == 64) {
            float a0 = 0.f, a1 = 0.f, c0 = 0.f, c1 = 0.f;
            int j = lo;
            for (; j + 1 < hi; j += 2) {
                int s0 = g_csr[j], s1 = g_csr[j + 1];
                float2 v0 = ((const float2*)(x + (size_t)s0 * 64))[lane];
                float2 v1 = ((const float2*)(x + (size_t)s1 * 64))[lane];
                if (SCALE_SRC) {
                    float ns0 = g_norm_src[s0], ns1 = g_norm_src[s1];
                    a0 = fmaf(v0.x, ns0, a0); a1 = fmaf(v0.y, ns0, a1);
                    c0 = fmaf(v1.x, ns1, c0); c1 = fmaf(v1.y, ns1, c1);
                } else {
                    a0 += v0.x; a1 += v0.y; c0 += v1.x; c1 += v1.y;
                }
            }
            if (j < hi) {
                int s0 = g_csr[j];
                float2 v0 = ((const float2*)(x + (size_t)s0 * 64))[lane];
                if (SCALE_SRC) {
                    float ns0 = g_norm_src[s0];
                    a0 = fmaf(v0.x, ns0, a0); a1 = fmaf(v0.y, ns0, a1);
                } else { a0 += v0.x; a1 += v0.y; }
            }
            float nd = g_norm_dst[n];
            float2 r; r.x = (a0 + c0) * nd; r.y = (a1 + c1) * nd;
            ((float2*)(smf + (size_t)(warp * 2 + t) * 64))[lane] = r;
        } else {
            float a0=0.f,a1=0.f,a2=0.f,a3=0.f,c0=0.f,c1=0.f,c2=0.f,c3=0.f;
            int j = lo;
            for (; j + 1 < hi; j += 2) {
                int s0 = g_csr[j], s1 = g_csr[j + 1];
                float4 v0 = ((const float4*)(x + (size_t)s0 * 128))[lane];
                float4 v1 = ((const float4*)(x + (size_t)s1 * 128))[lane];
                a0 += v0.x; a1 += v0.y; a2 += v0.z; a3 += v0.w;
                c0 += v1.x; c1 += v1.y; c2 += v1.z; c3 += v1.w;
            }
            if (j < hi) {
                int s0 = g_csr[j];
                float4 v0 = ((const float4*)(x + (size_t)s0 * 128))[lane];
                a0 += v0.x; a1 += v0.y; a2 += v0.z; a3 += v0.w;
            }
            float nd = g_norm_dst[n];
            float4 r;
            r.x = (a0 + c0) * nd; r.y = (a1 + c1) * nd;
            r.z = (a2 + c2) * nd; r.w = (a3 + c3) * nd;
            ((float4*)(smf + (size_t)(warp * 2 + t) * 128))[lane] = r;
        }
    }
    __syncthreads();

    // ---- phase B: GEMM from smem, R rows per thread ----
    int tx = tid % DOUT;
    int ty = tid / DOUT;
    float bias = b[tx];
    float acc[R];
#pragma unroll
    for (int r = 0; r < R; r++) acc[r] = bias;

    const float4* sm4 = (const float4*)smf;
#pragma unroll 4
    for (int k4 = 0; k4 < K4; k4++) {
        int k = k4 * 4;
        float w0 = W[(k + 0) * DOUT + tx];
        float w1 = W[(k + 1) * DOUT + tx];
        float w2 = W[(k + 2) * DOUT + tx];
        float w3 = W[(k + 3) * DOUT + tx];
#pragma unroll
        for (int r = 0; r < R; r++) {
            float4 v = sm4[(ty * R + r) * K4 + k4];
            acc[r] = fmaf(v.x, w0, acc[r]);
            acc[r] = fmaf(v.y, w1, acc[r]);
            acc[r] = fmaf(v.z, w2, acc[r]);
            acc[r] = fmaf(v.w, w3, acc[r]);
        }
    }

#pragma unroll
    for (int r = 0; r < R; r++) {
        size_t n = base + ty * R + r;
        float v = fmaxf(acc[r], 0.0f) * g_norm_src[n];
        out[n * DOUT + tx] = v;
    }
}

// ------- plain GEMM (layer-3 transform-first): out = m @ W3 ------------------
template <int DIN, int DOUT, int R>
__global__ void gemm_kernel(const float4* __restrict__ m4,
                            const float* __restrict__ W,
                            float* __restrict__ out) {
    constexpr int TY  = 256 / DOUT;
    constexpr int NPB = TY * R;
    constexpr int K4  = DIN / 4;
    __shared__ float4 sm[NPB * K4];
    int tx = threadIdx.x;
    int ty = threadIdx.y;
    int tid = ty * DOUT + tx;
    size_t base = (size_t)blockIdx.x * NPB;

    const float4* src = m4 + base * K4;
#pragma unroll
    for (int i = tid; i < NPB * K4; i += 256) sm[i] = src[i];
    __syncthreads();

    float acc[R];
#pragma unroll
    for (int r = 0; r < R; r++) acc[r] = 0.0f;

#pragma unroll 4
    for (int k4 = 0; k4 < K4; k4++) {
        int k = k4 * 4;
        float w0 = W[(k + 0) * DOUT + tx];
        float w1 = W[(k + 1) * DOUT + tx];
        float w2 = W[(k + 2) * DOUT + tx];
        float w3 = W[(k + 3) * DOUT + tx];
#pragma unroll
        for (int r = 0; r < R; r++) {
            float4 v = sm[(ty * R + r) * K4 + k4];
            acc[r] = fmaf(v.x, w0, acc[r]);
            acc[r] = fmaf(v.y, w1, acc[r]);
            acc[r] = fmaf(v.z, w2, acc[r]);
            acc[r] = fmaf(v.w, w3, acc[r]);
        }
    }

#pragma unroll
    for (int r = 0; r < R; r++) {
        size_t n = base + ty * R + r;
        out[n * DOUT + tx] = acc[r];
    }
}

// final layer gather: epilogue = relu(acc*nd + b3) then pooled atomicAdd
__global__ void gather_pool_kernel(const float* __restrict__ x,
                                   const float* __restrict__ b3,
                                   const void* __restrict__ gid,
                                   float* __restrict__ out) {
    int warp = (blockIdx.x << 3) | (threadIdx.x >> 5);
    int lane = threadIdx.x & 31;
    if (warp >= N_NODES) return;
    int lo = g_row[warp], hi = g_row[warp + 1];
    float a0 = 0.f, a1 = 0.f, c0 = 0.f, c1 = 0.f;
    int j = lo;
    for (; j + 1 < hi; j += 2) {
        int s0 = g_csr[j], s1 = g_csr[j + 1];
        float2 v0 = ((const float2*)(x + (size_t)s0 * 64))[lane];
        float2 v1 = ((const float2*)(x + (size_t)s1 * 64))[lane];
        a0 += v0.x; a1 += v0.y;
        c0 += v1.x; c1 += v1.y;
    }
    if (j < hi) {
        int s0 = g_csr[j];
        float2 v0 = ((const float2*)(x + (size_t)s0 * 64))[lane];
        a0 += v0.x; a1 += v0.y;
    }
    float nd = g_norm_dst[warp];
    float2 bb = ((const float2*)b3)[lane];
    float r0 = fmaxf(fmaf(a0 + c0, nd, bb.x), 0.0f);
    float r1 = fmaxf(fmaf(a1 + c1, nd, bb.y), 0.0f);
    int g = load_idx(gid, warp, g_flag_gid);
    atomicAdd(&out[(size_t)g * 64 + lane * 2],     r0);
    atomicAdd(&out[(size_t)g * 64 + lane * 2 + 1], r1);
}

// ---------------- launch ------------------------------------------------------
extern "C" void kernel_launch(void* const* d_in, const int* in_sizes, int n_in,
                              void* d_out, int out_size) {
    const float* h        = (const float*)d_in[0];
    const void*  src      = d_in[1];
    const void*  dst      = d_in[2];
    const void*  graph_id = d_in[3];
    const float* W1 = (const float*)d_in[4];
    const float* b1 = (const float*)d_in[5];
    const float* W2 = (const float*)d_in[6];
    const float* b2 = (const float*)d_in[7];
    const float* W3 = (const float*)d_in[8];
    const float* b3 = (const float*)d_in[9];
    float* out = (float*)d_out;

    float *pA, *pB;
    cudaGetSymbolAddress((void**)&pA, g_bufA);
    cudaGetSymbolAddress((void**)&pB, g_bufB);

    // 0: init (+dtype detect)   1: degrees   2: scan+norms   3: CSR fill
    init_kernel<<<(N_NODES + 255) / 256, 256>>>((const unsigned*)src,
                                                (const unsigned*)graph_id);
    deg_kernel<<<2048, 256>>>(src, dst);
    scan_norm_kernel<<<1, 1024>>>();
    fill_csr_kernel<<<2048, 256>>>(src, dst);

    // 4: layer 1 fused (gather 64 w/ per-edge norm_src, GEMM 64->128) h -> bufA
    fused_layer_kernel<64, 128, 1><<<N_NODES / 16, 256>>>(h, W1, b1, pA);

    // 5: layer 2 fused (gather 128, GEMM 128->128) bufA -> bufB
    fused_layer_kernel<128, 128, 0><<<N_NODES / 16, 256>>>(pA, W2, b2, pB);

    // 6: layer 3 transform-first GEMM 128->64 (no epilogue) bufB -> bufA
    {
        dim3 blk(64, 4);
        gemm_kernel<128, 64, 8><<<N_NODES / 32, blk>>>((const float4*)pB, W3, pA);
    }

    // 7: zero output   8: gather + relu + pooled atomics
    zero_out_kernel<<<(N_GRAPHS * 64 + 255) / 256, 256>>>(out, N_GRAPHS * 64);
    gather_pool_kernel<<<(N_NODES + 7) / 8, 256>>>(pA, b3, graph_id, out);
}